// round 1
// baseline (speedup 1.0000x reference)
#include <cuda_runtime.h>
#include <math_constants.h>

// Batched nearest-neighbor argmin + gather.
//   y:      [B, 2]       float32
//   Y_surf: [B, 2, G]    float32   (row b: 2 contiguous rows of length G)
//   U_grid: [2, G]       float32
//   out:    [B, 2]       float32   out[b,:] = U_grid[:, argmin_g ||Y_surf[b,:,g]-y[b,:]||^2]
//
// HBM-bound: 327.7 MB single-pass stream of Y_surf. One CTA per sample,
// 128 threads, float4 loads, block argmin reduction with first-index tie-break.

#define NT 128

__device__ __forceinline__ void upd(float d, int g, float& best, int& bidx) {
    // strict < keeps the earliest index within a thread's increasing-g scan
    if (d < best) { best = d; bidx = g; }
}

__global__ __launch_bounds__(NT, 8)
void lqr_argmin_kernel(const float* __restrict__ y,
                       const float* __restrict__ Ys,
                       const float* __restrict__ Ug,
                       float* __restrict__ out,
                       int G) {
    const int b   = blockIdx.x;
    const int tid = threadIdx.x;

    const float y0 = y[2 * b + 0];
    const float y1 = y[2 * b + 1];

    const float* __restrict__ r0 = Ys + (size_t)b * 2 * G;
    const float* __restrict__ r1 = r0 + G;

    float best = CUDART_INF_F;
    int   bidx = 0;

    if ((G & 3) == 0) {
        // Vector path: rows are 16B-aligned since G % 4 == 0.
        const int n4 = G >> 2;
        const float4* __restrict__ v0 = reinterpret_cast<const float4*>(r0);
        const float4* __restrict__ v1 = reinterpret_cast<const float4*>(r1);
        for (int i = tid; i < n4; i += NT) {
            float4 a = v0[i];
            float4 c = v1[i];
            int g = i << 2;
            float dx, dz, d;
            dx = a.x - y0; dz = c.x - y1; d = dx * dx + dz * dz; upd(d, g + 0, best, bidx);
            dx = a.y - y0; dz = c.y - y1; d = dx * dx + dz * dz; upd(d, g + 1, best, bidx);
            dx = a.z - y0; dz = c.z - y1; d = dx * dx + dz * dz; upd(d, g + 2, best, bidx);
            dx = a.w - y0; dz = c.w - y1; d = dx * dx + dz * dz; upd(d, g + 3, best, bidx);
        }
    } else {
        for (int g = tid; g < G; g += NT) {
            float dx = r0[g] - y0;
            float dz = r1[g] - y1;
            upd(dx * dx + dz * dz, g, best, bidx);
        }
    }

    // Warp reduction: min d2, tie -> min idx (matches jnp.argmin first-min).
    #pragma unroll
    for (int off = 16; off > 0; off >>= 1) {
        float ob = __shfl_down_sync(0xffffffffu, best, off);
        int   oi = __shfl_down_sync(0xffffffffu, bidx, off);
        if (ob < best || (ob == best && oi < bidx)) { best = ob; bidx = oi; }
    }

    __shared__ float sb[NT / 32];
    __shared__ int   si[NT / 32];
    const int w = tid >> 5;
    if ((tid & 31) == 0) { sb[w] = best; si[w] = bidx; }
    __syncthreads();

    if (w == 0) {
        const int nw = NT / 32;
        best = (tid < nw) ? sb[tid] : CUDART_INF_F;
        bidx = (tid < nw) ? si[tid] : 0x7fffffff;
        #pragma unroll
        for (int off = 16; off > 0; off >>= 1) {
            float ob = __shfl_down_sync(0xffffffffu, best, off);
            int   oi = __shfl_down_sync(0xffffffffu, bidx, off);
            if (ob < best || (ob == best && oi < bidx)) { best = ob; bidx = oi; }
        }
        if (tid == 0) {
            out[2 * b + 0] = Ug[bidx];
            out[2 * b + 1] = Ug[(size_t)G + bidx];
        }
    }
}

extern "C" void kernel_launch(void* const* d_in, const int* in_sizes, int n_in,
                              void* d_out, int out_size) {
    const float* y  = (const float*)d_in[0];   // [B, 2]
    const float* Ys = (const float*)d_in[1];   // [B, 2, G]
    const float* Ug = (const float*)d_in[2];   // [2, G]
    float* out = (float*)d_out;                // [B, 2]

    const int B = in_sizes[0] / 2;
    const int G = in_sizes[2] / 2;

    lqr_argmin_kernel<<<B, NT>>>(y, Ys, Ug, out, G);
}